// round 13
// baseline (speedup 1.0000x reference)
#include <cuda_runtime.h>
#include <cuda_fp16.h>
#include <math.h>
#include <stdint.h>

#define NQ   512
#define NC   16
#define CS   64
#define HID  128
#define NB   2048
#define ROUNDS 2
#define BPRD   8          // batches per round
#define GRID   148
#define THREADS 768
#define NWARP  24

#define WST  272          // padded fp16 row stride in bytes (128 halfs + 8 pad)

// ---- smem offsets ----
#define OFF_TAB  0                          // 512*256    = 131072
#define OFF_W    131072                     // 128*272    = 34816
#define OFF_M    165888                     // 128*272    = 34816 (raw ce tile)
#define OFF_BUF  200704                     // 8*16*64*2  = 16384
#define OFF_AN2  217088                     // 256*8      = 2048
#define OFF_BIAS 219136                     // 512
#define OFF_CNT  219648                     // 8*16*4     = 512
#define OFF_TMP  220160                     // 8*16*4     = 512
#define SMEM_REQ 220672

__device__ float g_anorm[NC * NC];
__device__ __align__(16) __half g_embh[(NQ + 1) * HID];
__device__ __align__(16) __half g_Wh[HID * HID];   // W[o][h], fp16

typedef unsigned long long u64;

static __device__ __forceinline__ uint32_t smem_u32(const void* p) {
    uint32_t a;
    asm("{ .reg .u64 t; cvta.to.shared.u64 t, %1; cvt.u32.u64 %0, t; }" : "=r"(a) : "l"(p));
    return a;
}
static __device__ __forceinline__ u64 pack2(float lo, float hi) {
    u64 r; asm("mov.b64 %0, {%1, %2};" : "=l"(r) : "f"(lo), "f"(hi)); return r;
}
static __device__ __forceinline__ void ffma2(u64 &d, u64 a, u64 b) {
    asm("fma.rn.f32x2 %0, %1, %2, %0;" : "+l"(d) : "l"(a), "l"(b));
}
static __device__ __forceinline__ float2 unpack2(u64 v) {
    float x, y; asm("mov.b64 {%0, %1}, %2;" : "=f"(x), "=f"(y) : "l"(v));
    return make_float2(x, y);
}
static __device__ __forceinline__ void ldsm_x4(uint32_t* r, uint32_t addr) {
    asm volatile("ldmatrix.sync.aligned.m8n8.x4.shared.b16 {%0,%1,%2,%3}, [%4];"
        : "=r"(r[0]), "=r"(r[1]), "=r"(r[2]), "=r"(r[3]) : "r"(addr));
}
static __device__ __forceinline__ void mma16816(float* d, const uint32_t* a, const uint32_t* b) {
    asm volatile("mma.sync.aligned.m16n8k16.row.col.f32.f16.f16.f32 "
        "{%0,%1,%2,%3}, {%4,%5,%6,%7}, {%8,%9}, {%0,%1,%2,%3};"
        : "+f"(d[0]), "+f"(d[1]), "+f"(d[2]), "+f"(d[3])
        : "r"(a[0]), "r"(a[1]), "r"(a[2]), "r"(a[3]), "r"(b[0]), "r"(b[1]));
}
#define CP_ASYNC16(dst, src) \
    asm volatile("cp.async.cg.shared.global [%0], [%1], 16;" :: "r"(dst), "l"(src))
#define CP_COMMIT() asm volatile("cp.async.commit_group;" ::: "memory")
#define CP_WAIT0()  asm volatile("cp.async.wait_group 0;" ::: "memory")

// ---------------- prep: anorm, fp16 table, fp16 W ----------------
__global__ void prep_kernel(const float* __restrict__ adj,
                            const float* __restrict__ W,
                            const float* __restrict__ qemb) {
    int t = threadIdx.x, b = blockIdx.x;
    if (b < 64) {
        int idx = b * 256 + t;                 // 16384 W entries
        g_Wh[idx] = __float2half(W[idx]);
    } else if (b == 64) {
        int i = t >> 4, j = t & 15;
        float di = 0.f, dj = 0.f;
#pragma unroll
        for (int r = 0; r < NC; r++) { di += adj[r * NC + i]; dj += adj[r * NC + j]; }
        di = di > 0.f ? rsqrtf(di) : 0.f;
        dj = dj > 0.f ? rsqrtf(dj) : 0.f;
        g_anorm[t] = adj[t] * di * dj;
    } else {
        int idx = (b - 65) * 256 + t;
        if (idx < (NQ + 1) * HID) g_embh[idx] = __float2half(qemb[idx]);
    }
}

// atomic-free bucket: match_any ranks + register counters (exact counts; unordered
// positions are safe because max over <=64 members is order-free; >64 falls back).
static __device__ __forceinline__ void bucket_match(
    const int* __restrict__ la, size_t batch,
    int wslot, int lane, unsigned short* s_buf, int* s_cnt, int* s_tmp)
{
    unsigned short* bw = s_buf + wslot * NC * CS;
    int* tw = s_tmp + wslot * NC;
    const unsigned lt = (1u << lane) - 1u;
    const int* lr = la + batch * NQ;
    if (lane < NC) tw[lane] = 0;
    int cnt = 0;
    __syncwarp();
#pragma unroll
    for (int g = 0; g < 16; g++) {
        const int a = __ldg(lr + g * 32 + lane);
        unsigned m = __match_any_sync(0xFFFFFFFFu, a);
        int base = __shfl_sync(0xFFFFFFFFu, cnt, a);
        int pos = base + __popc(m & lt);
        if (pos < CS) bw[a * CS + pos] = (unsigned short)(g * 32 + lane);
        if ((m & lt) == 0u) tw[a] = __popc(m);      // leader publishes group count
        __syncwarp();
        if (lane < NC) { cnt += tw[lane]; tw[lane] = 0; }
        __syncwarp();
    }
    if (lane < NC) s_cnt[wslot * NC + lane] = cnt;
    // rare overflow: rewrite in exact qubit order (counts already exact)
    bool ovf = (lane < NC) && (cnt > CS);
    if (__any_sync(0xFFFFFFFFu, ovf)) {
        if (lane == 0) {
            int c2[NC];
#pragma unroll
            for (int c = 0; c < NC; c++) c2[c] = 0;
            for (int q = 0; q < NQ; q++) {
                int c = lr[q];
                int p = c2[c];
                if (p < CS) bw[c * CS + p] = (unsigned short)q;
                c2[c] = p + 1;
            }
        }
        __syncwarp();
    }
}

// ---------------- fused: smem table -> bucket -> pool -> GEMM + epilogue-mix ----------------
__global__ void __launch_bounds__(THREADS, 1)
enc_kernel(const int*   __restrict__ la,
           const float* __restrict__ bias,
           float*       __restrict__ out)
{
    extern __shared__ __align__(16) char smem[];
    const uint32_t sb = smem_u32(smem);

    const int tid  = threadIdx.x;
    const int lane = tid & 31;
    const int w    = tid >> 5;
    const int blk  = blockIdx.x;

    // 2048 = 124*14 + 24*13
    const int b0     = blk * 13 + (blk < 124 ? blk : 124);
    const int nbatch = 13 + (blk < 124 ? 1 : 0);

    unsigned short* s_buf  = (unsigned short*)(smem + OFF_BUF);  // [8][16][64]
    int*            s_cnt  = (int*)(smem + OFF_CNT);             // [8][16]
    int*            s_tmp  = (int*)(smem + OFF_TMP);             // [8][16]
    u64*            s_an2  = (u64*)(smem + OFF_AN2);             // an pairs [i][j]
    float*          s_bias = (float*)(smem + OFF_BIAS);

    // ---- prologue: warps 8-23 cp.async consts/table/W; warps 0-7 bucket round 0 ----
    if (w >= 8) {
        const int t2 = tid - 256;   // 0..511
        if (t2 < 256) { float a = g_anorm[t2]; s_an2[t2] = pack2(a, a); }
        if (t2 < 128) s_bias[t2] = bias[t2];
        const char* tsrc = (const char*)g_embh;
#pragma unroll
        for (int i = 0; i < 16; i++) {
            int idx = i * 512 + t2;                        // 8192 x 16B
            CP_ASYNC16(sb + OFF_TAB + idx * 16, tsrc + idx * 16);
        }
        const char* wsrc = (const char*)g_Wh;
#pragma unroll
        for (int k = 0; k < 4; k++) {
            int idx = k * 512 + t2;                        // 2048 x 16B
            int o = idx >> 4, seg = idx & 15;
            CP_ASYNC16(sb + OFF_W + o * WST + seg * 16, wsrc + idx * 16);
        }
        CP_COMMIT();
        CP_WAIT0();
    } else {
        bucket_match(la, (size_t)(b0 + w), w, lane, s_buf, s_cnt, s_tmp);
    }
    __syncthreads();

    for (int R = 0; R < ROUNDS; R++) {
        const int nb = min(BPRD, nbatch - R * BPRD);   // active batches this round

        // ---- pool: 24 warps over nb*16 single-core jobs; ce -> M-tile rows ----
        for (int job = w; job < nb * NC; job += NWARP) {
            const int bb = job >> 4;
            const int c  = job & 15;
            int cnt = s_cnt[bb * NC + c];
            int n = cnt < CS ? cnt : CS;
            __half2 hini = __half2half2(__ushort_as_half(
                               (unsigned short)(cnt >= CS ? 0xFC00 : 0)));
            __half2 s0a = hini, s0b = hini, s1a = hini, s1b = hini;  // 2 streams
            const unsigned short* bq = &s_buf[(bb * NC + c) * CS];
            int i = 0;
            for (; i + 4 <= n; i += 4) {
                u64 qq = *(const u64*)(bq + i);
                uint32_t q0 = (uint32_t)(qq) & 0xFFFFu;
                uint32_t q1 = (uint32_t)(qq >> 16) & 0xFFFFu;
                uint32_t q2 = (uint32_t)(qq >> 32) & 0xFFFFu;
                uint32_t q3 = (uint32_t)(qq >> 48) & 0xFFFFu;
                uint2 r0 = *(const uint2*)(smem + OFF_TAB + q0 * 256u + lane * 8u);
                uint2 r1 = *(const uint2*)(smem + OFF_TAB + q1 * 256u + lane * 8u);
                uint2 r2 = *(const uint2*)(smem + OFF_TAB + q2 * 256u + lane * 8u);
                uint2 r3 = *(const uint2*)(smem + OFF_TAB + q3 * 256u + lane * 8u);
                s0a = __hmax2(s0a, *(__half2*)&r0.x); s0b = __hmax2(s0b, *(__half2*)&r0.y);
                s1a = __hmax2(s1a, *(__half2*)&r1.x); s1b = __hmax2(s1b, *(__half2*)&r1.y);
                s0a = __hmax2(s0a, *(__half2*)&r2.x); s0b = __hmax2(s0b, *(__half2*)&r2.y);
                s1a = __hmax2(s1a, *(__half2*)&r3.x); s1b = __hmax2(s1b, *(__half2*)&r3.y);
            }
            for (; i < n; i++) {
                uint32_t q = bq[i];
                uint2 r0 = *(const uint2*)(smem + OFF_TAB + q * 256u + lane * 8u);
                s0a = __hmax2(s0a, *(__half2*)&r0.x); s0b = __hmax2(s0b, *(__half2*)&r0.y);
            }
            __half2 a0 = __hmax2(s0a, s1a);
            __half2 a1 = __hmax2(s0b, s1b);
            uint2 st;
            st.x = *(uint32_t*)&a0; st.y = *(uint32_t*)&a1;
            *(uint2*)(smem + OFF_M + (bb * NC + c) * WST + lane * 8) = st;
        }
        __syncthreads();

        // ---- GEMM (warps 8-23) + bucket(R+1) on warps 0-7 ----
        if (w < 8) {
            const int nr = R + 1;
            if (nr < ROUNDS && nr * BPRD + w < nbatch)
                bucket_match(la, (size_t)(b0 + nr * BPRD + w), w, lane, s_buf, s_cnt, s_tmp);
        } else {
            const int wg  = w - 8;
            const int rt8 = wg >> 1;     // batch in round (16 rows)
            const int ch  = wg & 1;      // 64-col half
            const int g   = lane >> 2, t4 = lane & 3;

            float d[2][4][4];            // 2 col sub-tiles of 32
#pragma unroll
            for (int t = 0; t < 2; t++)
#pragma unroll
                for (int nt = 0; nt < 4; nt++)
#pragma unroll
                    for (int k = 0; k < 4; k++) d[t][nt][k] = 0.f;

            const uint32_t aBase = sb + OFF_M
                + (uint32_t)(rt8 * 16 + (lane & 15)) * WST + (uint32_t)((lane >> 4) * 16);
            const uint32_t bBase0 = sb + OFF_W
                + (uint32_t)(ch * 64 + (lane & 7) + ((lane >> 4) * 8)) * WST
                + (uint32_t)(((lane >> 3) & 1) * 16);
            const uint32_t bBase1 = bBase0 + 16 * WST;
            const uint32_t bBase2 = bBase0 + 32 * WST;
            const uint32_t bBase3 = bBase0 + 48 * WST;

#pragma unroll
            for (int s = 0; s < 8; s++) {
                uint32_t a[4], b0r[4], b1r[4], b2r[4], b3r[4];
                ldsm_x4(a,   aBase  + s * 32);
                ldsm_x4(b0r, bBase0 + s * 32);
                ldsm_x4(b1r, bBase1 + s * 32);
                ldsm_x4(b2r, bBase2 + s * 32);
                ldsm_x4(b3r, bBase3 + s * 32);
                mma16816(d[0][0], a, b0r + 0);
                mma16816(d[0][1], a, b0r + 2);
                mma16816(d[0][2], a, b1r + 0);
                mma16816(d[0][3], a, b1r + 2);
                mma16816(d[1][0], a, b2r + 0);
                mma16816(d[1][1], a, b2r + 2);
                mma16816(d[1][2], a, b3r + 0);
                mma16816(d[1][3], a, b3r + 2);
            }

            // ---- epilogue: adjacency mix via warp shuffles (reference order), bias, store ----
            const bool wr = (rt8 < nb);
            float* ob = out + (size_t)(b0 + R * BPRD + rt8) * (NC * HID);
            float* o0 = ob + g * HID;
            float* o1 = ob + (g + 8) * HID;
#pragma unroll
            for (int t = 0; t < 2; t++) {
                u64 acc0[4], acc1[4];    // acc0: row g, acc1: row g+8; f32x2 col pairs
#pragma unroll
                for (int nt = 0; nt < 4; nt++) { acc0[nt] = 0ull; acc1[nt] = 0ull; }
#pragma unroll
                for (int src = 0; src < 8; src++) {
                    const int sl = src * 4 + t4;
                    u64 an_g_s   = s_an2[g * NC + src];
                    u64 an_g_s8  = s_an2[g * NC + src + 8];
                    u64 an_g8_s  = s_an2[(g + 8) * NC + src];
                    u64 an_g8_s8 = s_an2[(g + 8) * NC + src + 8];
#pragma unroll
                    for (int nt = 0; nt < 4; nt++) {
                        float h0 = __shfl_sync(0xFFFFFFFFu, d[t][nt][0], sl);
                        float h1 = __shfl_sync(0xFFFFFFFFu, d[t][nt][1], sl);
                        float h2 = __shfl_sync(0xFFFFFFFFu, d[t][nt][2], sl);
                        float h3 = __shfl_sync(0xFFFFFFFFu, d[t][nt][3], sl);
                        u64 hp_lo = pack2(h0, h1);   // row src,   col pair
                        u64 hp_hi = pack2(h2, h3);   // row src+8, col pair
                        ffma2(acc0[nt], hp_lo, an_g_s);
                        ffma2(acc0[nt], hp_hi, an_g_s8);
                        ffma2(acc1[nt], hp_lo, an_g8_s);
                        ffma2(acc1[nt], hp_hi, an_g8_s8);
                    }
                }
                if (wr) {
#pragma unroll
                    for (int nt = 0; nt < 4; nt++) {
                        int col = ch * 64 + t * 32 + nt * 8 + 2 * t4;
                        float bv0 = s_bias[col], bv1 = s_bias[col + 1];
                        float2 f0 = unpack2(acc0[nt]);
                        float2 f1 = unpack2(acc1[nt]);
                        *(float2*)(o0 + col) = make_float2(f0.x + bv0, f0.y + bv1);
                        *(float2*)(o1 + col) = make_float2(f1.x + bv0, f1.y + bv1);
                    }
                }
            }
        }
        __syncthreads();   // M tile consumed + next buckets ready before next round
    }
}

extern "C" void kernel_launch(void* const* d_in, const int* in_sizes, int n_in,
                              void* d_out, int out_size) {
    const int*   la   = (const int*)  d_in[0];   // (2048, 512) int32
    const float* adj  = (const float*)d_in[1];   // (16, 16) f32
    const float* qemb = (const float*)d_in[2];   // (513, 128) f32
    const float* W    = (const float*)d_in[3];   // (128, 128) f32
    const float* bias = (const float*)d_in[4];   // (128,) f32
    float* out = (float*)d_out;                  // (2048, 16, 128) f32

    cudaFuncSetAttribute(enc_kernel, cudaFuncAttributeMaxDynamicSharedMemorySize, SMEM_REQ);
    prep_kernel<<<322, 256>>>(adj, W, qemb);
    enc_kernel<<<GRID, THREADS, SMEM_REQ>>>(la, bias, out);
}

// round 14
// speedup vs baseline: 1.1813x; 1.1813x over previous
#include <cuda_runtime.h>
#include <cuda_fp16.h>
#include <math.h>
#include <stdint.h>

#define NQ   512
#define NC   16
#define CS   64
#define HID  128
#define NB   2048
#define ROUNDS 2
#define BPRD   8          // batches per round
#define GRID   148
#define THREADS 768
#define NWARP  24

#define WST  272          // padded fp16 row stride in bytes (128 halfs + 8 pad)

// ---- smem offsets ----
#define OFF_TAB  0                          // 512*256    = 131072
#define OFF_W    131072                     // 128*272    = 34816
#define OFF_M    165888                     // 128*272    = 34816 (ce, then mixed m, in place)
#define OFF_BUF  200704                     // 8*16*64*2  = 16384
#define OFF_AN2  217088                     // 256*8      = 2048
#define OFF_BIAS 219136                     // 512
#define OFF_CNT  219648                     // 8*16*4     = 512
#define OFF_TMP  220160                     // 8*16*4     = 512
#define SMEM_REQ 220672

__device__ float g_anorm[NC * NC];
__device__ __align__(16) __half g_embh[(NQ + 1) * HID];
__device__ __align__(16) __half g_Wh[HID * HID];   // W[o][h], fp16

typedef unsigned long long u64;

static __device__ __forceinline__ uint32_t smem_u32(const void* p) {
    uint32_t a;
    asm("{ .reg .u64 t; cvta.to.shared.u64 t, %1; cvt.u32.u64 %0, t; }" : "=r"(a) : "l"(p));
    return a;
}
static __device__ __forceinline__ u64 pack2(float lo, float hi) {
    u64 r; asm("mov.b64 %0, {%1, %2};" : "=l"(r) : "f"(lo), "f"(hi)); return r;
}
static __device__ __forceinline__ void ffma2(u64 &d, u64 a, u64 b) {
    asm("fma.rn.f32x2 %0, %1, %2, %0;" : "+l"(d) : "l"(a), "l"(b));
}
static __device__ __forceinline__ float2 unpack2(u64 v) {
    float x, y; asm("mov.b64 {%0, %1}, %2;" : "=f"(x), "=f"(y) : "l"(v));
    return make_float2(x, y);
}
static __device__ __forceinline__ void ldsm_x4(uint32_t* r, uint32_t addr) {
    asm volatile("ldmatrix.sync.aligned.m8n8.x4.shared.b16 {%0,%1,%2,%3}, [%4];"
        : "=r"(r[0]), "=r"(r[1]), "=r"(r[2]), "=r"(r[3]) : "r"(addr));
}
static __device__ __forceinline__ void mma16816(float* d, const uint32_t* a, const uint32_t* b) {
    asm volatile("mma.sync.aligned.m16n8k16.row.col.f32.f16.f16.f32 "
        "{%0,%1,%2,%3}, {%4,%5,%6,%7}, {%8,%9}, {%0,%1,%2,%3};"
        : "+f"(d[0]), "+f"(d[1]), "+f"(d[2]), "+f"(d[3])
        : "r"(a[0]), "r"(a[1]), "r"(a[2]), "r"(a[3]), "r"(b[0]), "r"(b[1]));
}
#define CP_ASYNC16(dst, src) \
    asm volatile("cp.async.cg.shared.global [%0], [%1], 16;" :: "r"(dst), "l"(src))
#define CP_COMMIT() asm volatile("cp.async.commit_group;" ::: "memory")
#define CP_WAIT0()  asm volatile("cp.async.wait_group 0;" ::: "memory")

// ---------------- prep: anorm, fp16 table, fp16 W ----------------
__global__ void prep_kernel(const float* __restrict__ adj,
                            const float* __restrict__ W,
                            const float* __restrict__ qemb) {
    int t = threadIdx.x, b = blockIdx.x;
    if (b < 64) {
        int idx = b * 256 + t;                 // 16384 W entries
        g_Wh[idx] = __float2half(W[idx]);
    } else if (b == 64) {
        int i = t >> 4, j = t & 15;
        float di = 0.f, dj = 0.f;
#pragma unroll
        for (int r = 0; r < NC; r++) { di += adj[r * NC + i]; dj += adj[r * NC + j]; }
        di = di > 0.f ? rsqrtf(di) : 0.f;
        dj = dj > 0.f ? rsqrtf(dj) : 0.f;
        g_anorm[t] = adj[t] * di * dj;
    } else {
        int idx = (b - 65) * 256 + t;
        if (idx < (NQ + 1) * HID) g_embh[idx] = __float2half(qemb[idx]);
    }
}

// atomic-free bucket: match_any ranks + register counters (exact counts; unordered
// positions are safe because max over <=64 members is order-free; >64 falls back).
static __device__ __forceinline__ void bucket_match(
    const int* __restrict__ la, size_t batch,
    int wslot, int lane, unsigned short* s_buf, int* s_cnt, int* s_tmp)
{
    unsigned short* bw = s_buf + wslot * NC * CS;
    int* tw = s_tmp + wslot * NC;
    const unsigned lt = (1u << lane) - 1u;
    const int* lr = la + batch * NQ;
    if (lane < NC) tw[lane] = 0;
    int cnt = 0;
    __syncwarp();
#pragma unroll
    for (int g = 0; g < 16; g++) {
        const int a = __ldg(lr + g * 32 + lane);
        unsigned m = __match_any_sync(0xFFFFFFFFu, a);
        int base = __shfl_sync(0xFFFFFFFFu, cnt, a);
        int pos = base + __popc(m & lt);
        if (pos < CS) bw[a * CS + pos] = (unsigned short)(g * 32 + lane);
        if ((m & lt) == 0u) tw[a] = __popc(m);      // leader publishes group count
        __syncwarp();
        if (lane < NC) { cnt += tw[lane]; tw[lane] = 0; }
        __syncwarp();
    }
    if (lane < NC) s_cnt[wslot * NC + lane] = cnt;
    // rare overflow: rewrite in exact qubit order (counts already exact)
    bool ovf = (lane < NC) && (cnt > CS);
    if (__any_sync(0xFFFFFFFFu, ovf)) {
        if (lane == 0) {
            int c2[NC];
#pragma unroll
            for (int c = 0; c < NC; c++) c2[c] = 0;
            for (int q = 0; q < NQ; q++) {
                int c = lr[q];
                int p = c2[c];
                if (p < CS) bw[c * CS + p] = (unsigned short)q;
                c2[c] = p + 1;
            }
        }
        __syncwarp();
    }
}

// ---------------- fused: smem table -> bucket -> pool -> (mix || bucket) -> GEMM ----------------
__global__ void __launch_bounds__(THREADS, 1)
enc_kernel(const int*   __restrict__ la,
           const float* __restrict__ bias,
           float*       __restrict__ out)
{
    extern __shared__ __align__(16) char smem[];
    const uint32_t sb = smem_u32(smem);

    const int tid  = threadIdx.x;
    const int lane = tid & 31;
    const int w    = tid >> 5;
    const int blk  = blockIdx.x;

    // 2048 = 124*14 + 24*13
    const int b0     = blk * 13 + (blk < 124 ? blk : 124);
    const int nbatch = 13 + (blk < 124 ? 1 : 0);

    unsigned short* s_buf  = (unsigned short*)(smem + OFF_BUF);  // [8][16][64]
    int*            s_cnt  = (int*)(smem + OFF_CNT);             // [8][16]
    int*            s_tmp  = (int*)(smem + OFF_TMP);             // [8][16]
    u64*            s_an2  = (u64*)(smem + OFF_AN2);             // an pairs [i][j]
    float*          s_bias = (float*)(smem + OFF_BIAS);

    // ---- prologue: warps 8-23 cp.async consts/table/W; warps 0-7 bucket round 0 ----
    if (w >= 8) {
        const int t2 = tid - 256;   // 0..511
        if (t2 < 256) { float a = g_anorm[t2]; s_an2[t2] = pack2(a, a); }
        if (t2 < 128) s_bias[t2] = bias[t2];
        const char* tsrc = (const char*)g_embh;
#pragma unroll
        for (int i = 0; i < 16; i++) {
            int idx = i * 512 + t2;                        // 8192 x 16B
            CP_ASYNC16(sb + OFF_TAB + idx * 16, tsrc + idx * 16);
        }
        const char* wsrc = (const char*)g_Wh;
#pragma unroll
        for (int k = 0; k < 4; k++) {
            int idx = k * 512 + t2;                        // 2048 x 16B
            int o = idx >> 4, seg = idx & 15;
            CP_ASYNC16(sb + OFF_W + o * WST + seg * 16, wsrc + idx * 16);
        }
        CP_COMMIT();
        CP_WAIT0();
    } else {
        bucket_match(la, (size_t)(b0 + w), w, lane, s_buf, s_cnt, s_tmp);
    }
    __syncthreads();

    for (int R = 0; R < ROUNDS; R++) {
        const int nb = min(BPRD, nbatch - R * BPRD);   // active batches this round

        // ---- pool: 24 warps over nb*16 single-core jobs; ce -> M-tile rows ----
        for (int job = w; job < nb * NC; job += NWARP) {
            const int bb = job >> 4;
            const int c  = job & 15;
            int cnt = s_cnt[bb * NC + c];
            int n = cnt < CS ? cnt : CS;
            __half2 hini = __half2half2(__ushort_as_half(
                               (unsigned short)(cnt >= CS ? 0xFC00 : 0)));
            __half2 s0a = hini, s0b = hini, s1a = hini, s1b = hini;  // 2 streams
            const unsigned short* bq = &s_buf[(bb * NC + c) * CS];
            int i = 0;
            for (; i + 4 <= n; i += 4) {
                u64 qq = *(const u64*)(bq + i);
                uint32_t q0 = (uint32_t)(qq) & 0xFFFFu;
                uint32_t q1 = (uint32_t)(qq >> 16) & 0xFFFFu;
                uint32_t q2 = (uint32_t)(qq >> 32) & 0xFFFFu;
                uint32_t q3 = (uint32_t)(qq >> 48) & 0xFFFFu;
                uint2 r0 = *(const uint2*)(smem + OFF_TAB + q0 * 256u + lane * 8u);
                uint2 r1 = *(const uint2*)(smem + OFF_TAB + q1 * 256u + lane * 8u);
                uint2 r2 = *(const uint2*)(smem + OFF_TAB + q2 * 256u + lane * 8u);
                uint2 r3 = *(const uint2*)(smem + OFF_TAB + q3 * 256u + lane * 8u);
                s0a = __hmax2(s0a, *(__half2*)&r0.x); s0b = __hmax2(s0b, *(__half2*)&r0.y);
                s1a = __hmax2(s1a, *(__half2*)&r1.x); s1b = __hmax2(s1b, *(__half2*)&r1.y);
                s0a = __hmax2(s0a, *(__half2*)&r2.x); s0b = __hmax2(s0b, *(__half2*)&r2.y);
                s1a = __hmax2(s1a, *(__half2*)&r3.x); s1b = __hmax2(s1b, *(__half2*)&r3.y);
            }
            for (; i < n; i++) {
                uint32_t q = bq[i];
                uint2 r0 = *(const uint2*)(smem + OFF_TAB + q * 256u + lane * 8u);
                s0a = __hmax2(s0a, *(__half2*)&r0.x); s0b = __hmax2(s0b, *(__half2*)&r0.y);
            }
            __half2 a0 = __hmax2(s0a, s1a);
            __half2 a1 = __hmax2(s0b, s1b);
            uint2 st;
            st.x = *(uint32_t*)&a0; st.y = *(uint32_t*)&a1;
            *(uint2*)(smem + OFF_M + (bb * NC + c) * WST + lane * 8) = st;
        }
        __syncthreads();

        // ---- mix (warps 16-23, one batch each, in-warp read->write: race-free)
        //      || bucket(R+1) on warps 0-7; warps 8-15 idle ----
        if (w >= 16) {
            const int bb = w - 16;
            if (bb < nb) {
                uint2 v[NC];
#pragma unroll
                for (int j = 0; j < NC; j++)
                    v[j] = *(const uint2*)(smem + OFF_M + (bb * NC + j) * WST + lane * 8);
#pragma unroll
                for (int half = 0; half < 2; half++) {
                    u64 mlo[8], mhi[8];
#pragma unroll
                    for (int ii = 0; ii < 8; ii++) { mlo[ii] = 0ull; mhi[ii] = 0ull; }
#pragma unroll
                    for (int j = 0; j < NC; j++) {
                        float2 flo = __half22float2(*(__half2*)&v[j].x);
                        float2 fhi = __half22float2(*(__half2*)&v[j].y);
                        u64 vlo = pack2(flo.x, flo.y);
                        u64 vhi = pack2(fhi.x, fhi.y);
#pragma unroll
                        for (int ii = 0; ii < 8; ii++) {
                            u64 ap = s_an2[(half * 8 + ii) * NC + j];
                            ffma2(mlo[ii], vlo, ap);
                            ffma2(mhi[ii], vhi, ap);
                        }
                    }
#pragma unroll
                    for (int ii = 0; ii < 8; ii++) {
                        int r = bb * NC + half * 8 + ii;
                        float2 l = unpack2(mlo[ii]);
                        float2 h = unpack2(mhi[ii]);
                        __half2 h0 = __floats2half2_rn(l.x, l.y);
                        __half2 h1 = __floats2half2_rn(h.x, h.y);
                        uint2 st; st.x = *(uint32_t*)&h0; st.y = *(uint32_t*)&h1;
                        *(uint2*)(smem + OFF_M + r * WST + lane * 8) = st;
                    }
                }
            }
        } else if (w < 8) {
            const int nr = R + 1;
            if (nr < ROUNDS && nr * BPRD + w < nbatch)
                bucket_match(la, (size_t)(b0 + nr * BPRD + w), w, lane, s_buf, s_cnt, s_tmp);
        }
        __syncthreads();

        // ---- GEMM (warps 8-23, 16 tiles: batch x 64-col half) ----
        if (w >= 8) {
            const int wg  = w - 8;
            const int rt8 = wg >> 1;     // batch in round (16 rows)
            const int ch  = wg & 1;      // 64-col half

            float d[2][4][4];            // 2 col sub-tiles of 32
#pragma unroll
            for (int t = 0; t < 2; t++)
#pragma unroll
                for (int nt = 0; nt < 4; nt++)
#pragma unroll
                    for (int k = 0; k < 4; k++) d[t][nt][k] = 0.f;

            const uint32_t aBase = sb + OFF_M
                + (uint32_t)(rt8 * 16 + (lane & 15)) * WST + (uint32_t)((lane >> 4) * 16);
            const uint32_t bBase0 = sb + OFF_W
                + (uint32_t)(ch * 64 + (lane & 7) + ((lane >> 4) * 8)) * WST
                + (uint32_t)(((lane >> 3) & 1) * 16);
            const uint32_t bBase1 = bBase0 + 16 * WST;
            const uint32_t bBase2 = bBase0 + 32 * WST;
            const uint32_t bBase3 = bBase0 + 48 * WST;

#pragma unroll
            for (int s = 0; s < 8; s++) {
                uint32_t a[4], b0r[4], b1r[4], b2r[4], b3r[4];
                ldsm_x4(a,   aBase  + s * 32);
                ldsm_x4(b0r, bBase0 + s * 32);
                ldsm_x4(b1r, bBase1 + s * 32);
                ldsm_x4(b2r, bBase2 + s * 32);
                ldsm_x4(b3r, bBase3 + s * 32);
                mma16816(d[0][0], a, b0r + 0);
                mma16816(d[0][1], a, b0r + 2);
                mma16816(d[0][2], a, b1r + 0);
                mma16816(d[0][3], a, b1r + 2);
                mma16816(d[1][0], a, b2r + 0);
                mma16816(d[1][1], a, b2r + 2);
                mma16816(d[1][2], a, b3r + 0);
                mma16816(d[1][3], a, b3r + 2);
            }

            // ---- epilogue: bias + direct stores (guarded per batch) ----
            if (rt8 < nb) {
                const int g = lane >> 2, t4 = lane & 3;
                float* ob = out + (size_t)(b0 + R * BPRD + rt8) * (NC * HID);
                float* o0 = ob + g * HID;
                float* o1 = ob + (g + 8) * HID;
#pragma unroll
                for (int t = 0; t < 2; t++) {
#pragma unroll
                    for (int nt = 0; nt < 4; nt++) {
                        int col = ch * 64 + t * 32 + nt * 8 + 2 * t4;
                        float bv0 = s_bias[col], bv1 = s_bias[col + 1];
                        *(float2*)(o0 + col) = make_float2(d[t][nt][0] + bv0, d[t][nt][1] + bv1);
                        *(float2*)(o1 + col) = make_float2(d[t][nt][2] + bv0, d[t][nt][3] + bv1);
                    }
                }
            }
        }
        __syncthreads();   // M tile consumed + next buckets ready before next round
    }
}

extern "C" void kernel_launch(void* const* d_in, const int* in_sizes, int n_in,
                              void* d_out, int out_size) {
    const int*   la   = (const int*)  d_in[0];   // (2048, 512) int32
    const float* adj  = (const float*)d_in[1];   // (16, 16) f32
    const float* qemb = (const float*)d_in[2];   // (513, 128) f32
    const float* W    = (const float*)d_in[3];   // (128, 128) f32
    const float* bias = (const float*)d_in[4];   // (128,) f32
    float* out = (float*)d_out;                  // (2048, 16, 128) f32

    cudaFuncSetAttribute(enc_kernel, cudaFuncAttributeMaxDynamicSharedMemorySize, SMEM_REQ);
    prep_kernel<<<322, 256>>>(adj, W, qemb);
    enc_kernel<<<GRID, THREADS, SMEM_REQ>>>(la, bias, out);
}

// round 15
// speedup vs baseline: 1.3350x; 1.1301x over previous
#include <cuda_runtime.h>
#include <cuda_fp16.h>
#include <math.h>
#include <stdint.h>

#define NQ   512
#define NC   16
#define CS   64
#define HID  128
#define NB   2048
#define ROUNDS 2
#define BPRD   8          // batches per round
#define GRID   148
#define THREADS 512

#define WST  272          // padded fp16 row stride in bytes (128 halfs + 8 pad)

// ---- smem offsets ----
#define OFF_TAB  0                          // 512*256    = 131072
#define OFF_W    131072                     // 128*272    = 34816
#define OFF_M    165888                     // 128*272    = 34816 (ce, then mixed m, in place)
#define OFF_BUF  200704                     // 8*16*64*2  = 16384
#define OFF_AN2  217088                     // 256*8      = 2048
#define OFF_BIAS 219136                     // 512
#define OFF_CNT  219648                     // 8*16*4     = 512
#define OFF_TMP  220160                     // 8*16*4     = 512
#define SMEM_REQ 220672

__device__ float g_anorm[NC * NC];
__device__ __align__(16) __half g_embh[(NQ + 1) * HID];
__device__ __align__(16) __half g_Wh[HID * HID];   // W[o][h], fp16

typedef unsigned long long u64;

static __device__ __forceinline__ uint32_t smem_u32(const void* p) {
    uint32_t a;
    asm("{ .reg .u64 t; cvta.to.shared.u64 t, %1; cvt.u32.u64 %0, t; }" : "=r"(a) : "l"(p));
    return a;
}
static __device__ __forceinline__ u64 pack2(float lo, float hi) {
    u64 r; asm("mov.b64 %0, {%1, %2};" : "=l"(r) : "f"(lo), "f"(hi)); return r;
}
static __device__ __forceinline__ void ffma2(u64 &d, u64 a, u64 b) {
    asm("fma.rn.f32x2 %0, %1, %2, %0;" : "+l"(d) : "l"(a), "l"(b));
}
static __device__ __forceinline__ float2 unpack2(u64 v) {
    float x, y; asm("mov.b64 {%0, %1}, %2;" : "=f"(x), "=f"(y) : "l"(v));
    return make_float2(x, y);
}
static __device__ __forceinline__ void ldsm_x4(uint32_t* r, uint32_t addr) {
    asm volatile("ldmatrix.sync.aligned.m8n8.x4.shared.b16 {%0,%1,%2,%3}, [%4];"
        : "=r"(r[0]), "=r"(r[1]), "=r"(r[2]), "=r"(r[3]) : "r"(addr));
}
static __device__ __forceinline__ void mma16816(float* d, const uint32_t* a, const uint32_t* b) {
    asm volatile("mma.sync.aligned.m16n8k16.row.col.f32.f16.f16.f32 "
        "{%0,%1,%2,%3}, {%4,%5,%6,%7}, {%8,%9}, {%0,%1,%2,%3};"
        : "+f"(d[0]), "+f"(d[1]), "+f"(d[2]), "+f"(d[3])
        : "r"(a[0]), "r"(a[1]), "r"(a[2]), "r"(a[3]), "r"(b[0]), "r"(b[1]));
}
#define CP_ASYNC16(dst, src) \
    asm volatile("cp.async.cg.shared.global [%0], [%1], 16;" :: "r"(dst), "l"(src))
#define CP_COMMIT() asm volatile("cp.async.commit_group;" ::: "memory")
#define CP_WAIT0()  asm volatile("cp.async.wait_group 0;" ::: "memory")

// ---------------- prep: anorm, fp16 table, fp16 W ----------------
__global__ void prep_kernel(const float* __restrict__ adj,
                            const float* __restrict__ W,
                            const float* __restrict__ qemb) {
    int t = threadIdx.x, b = blockIdx.x;
    if (b < 64) {
        int idx = b * 256 + t;                 // 16384 W entries
        g_Wh[idx] = __float2half(W[idx]);
    } else if (b == 64) {
        int i = t >> 4, j = t & 15;
        float di = 0.f, dj = 0.f;
#pragma unroll
        for (int r = 0; r < NC; r++) { di += adj[r * NC + i]; dj += adj[r * NC + j]; }
        di = di > 0.f ? rsqrtf(di) : 0.f;
        dj = dj > 0.f ? rsqrtf(dj) : 0.f;
        g_anorm[t] = adj[t] * di * dj;
    } else {
        int idx = (b - 65) * 256 + t;
        if (idx < (NQ + 1) * HID) g_embh[idx] = __float2half(qemb[idx]);
    }
}

// atomic-free bucket: match_any ranks + register counters (exact counts; unordered
// positions are safe because max over <=64 members is order-free; >64 falls back).
static __device__ __forceinline__ void bucket_match(
    const int* __restrict__ la, size_t batch,
    int wslot, int lane, unsigned short* s_buf, int* s_cnt, int* s_tmp)
{
    unsigned short* bw = s_buf + wslot * NC * CS;
    int* tw = s_tmp + wslot * NC;
    const unsigned lt = (1u << lane) - 1u;
    const int* lr = la + batch * NQ;
    if (lane < NC) tw[lane] = 0;
    int cnt = 0;
    __syncwarp();
#pragma unroll
    for (int g = 0; g < 16; g++) {
        const int a = __ldg(lr + g * 32 + lane);
        unsigned m = __match_any_sync(0xFFFFFFFFu, a);
        int base = __shfl_sync(0xFFFFFFFFu, cnt, a);
        int pos = base + __popc(m & lt);
        if (pos < CS) bw[a * CS + pos] = (unsigned short)(g * 32 + lane);
        if ((m & lt) == 0u) tw[a] = __popc(m);      // leader publishes group count
        __syncwarp();
        if (lane < NC) { cnt += tw[lane]; tw[lane] = 0; }
        __syncwarp();
    }
    if (lane < NC) s_cnt[wslot * NC + lane] = cnt;
    // rare overflow: rewrite in exact qubit order (counts already exact)
    bool ovf = (lane < NC) && (cnt > CS);
    if (__any_sync(0xFFFFFFFFu, ovf)) {
        if (lane == 0) {
            int c2[NC];
#pragma unroll
            for (int c = 0; c < NC; c++) c2[c] = 0;
            for (int q = 0; q < NQ; q++) {
                int c = lr[q];
                int p = c2[c];
                if (p < CS) bw[c * CS + p] = (unsigned short)q;
                c2[c] = p + 1;
            }
        }
        __syncwarp();
    }
}

// ---------------- fused: smem table -> match-bucket -> pool -> mix -> GEMM(+bucket) ----------------
__global__ void __launch_bounds__(THREADS, 1)
enc_kernel(const int*   __restrict__ la,
           const float* __restrict__ bias,
           float*       __restrict__ out)
{
    extern __shared__ __align__(16) char smem[];
    const uint32_t sb = smem_u32(smem);

    const int tid  = threadIdx.x;
    const int lane = tid & 31;
    const int w    = tid >> 5;
    const int blk  = blockIdx.x;

    // 2048 = 124*14 + 24*13
    const int b0     = blk * 13 + (blk < 124 ? blk : 124);
    const int nbatch = 13 + (blk < 124 ? 1 : 0);

    unsigned short* s_buf  = (unsigned short*)(smem + OFF_BUF);  // [8][16][64]
    int*            s_cnt  = (int*)(smem + OFF_CNT);             // [8][16]
    int*            s_tmp  = (int*)(smem + OFF_TMP);             // [8][16]
    u64*            s_an2  = (u64*)(smem + OFF_AN2);             // an pairs [i][j]
    float*          s_bias = (float*)(smem + OFF_BIAS);

    // ---- prologue: warps 8-15 cp.async consts/table/W; warps 0-7 bucket round 0 ----
    if (w >= 8) {
        const int t2 = tid - 256;   // 0..255
        { float a = g_anorm[t2]; s_an2[t2] = pack2(a, a); }
        if (t2 < 128) s_bias[t2] = bias[t2];
        const char* tsrc = (const char*)g_embh;
#pragma unroll
        for (int i = 0; i < 32; i++) {
            int idx = i * 256 + t2;                        // 8192 x 16B
            CP_ASYNC16(sb + OFF_TAB + idx * 16, tsrc + idx * 16);
        }
        const char* wsrc = (const char*)g_Wh;
#pragma unroll
        for (int k = 0; k < 8; k++) {
            int idx = k * 256 + t2;                        // 2048 x 16B
            int o = idx >> 4, seg = idx & 15;
            CP_ASYNC16(sb + OFF_W + o * WST + seg * 16, wsrc + idx * 16);
        }
        CP_COMMIT();
        CP_WAIT0();
    } else {
        bucket_match(la, (size_t)(b0 + w), w, lane, s_buf, s_cnt, s_tmp);
    }
    __syncthreads();

    for (int R = 0; R < ROUNDS; R++) {
        const int nb = min(BPRD, nbatch - R * BPRD);   // active batches this round

        // ---- pool: warp -> (batch w>>1, cores (w&1)*8..+7); 2-stream accumulators ----
        {
            const int bb = w >> 1;
            if (bb < nb) {
                const int c0 = (w & 1) * 8;
#pragma unroll
                for (int cc = 0; cc < 8; cc++) {
                    int c = c0 + cc;
                    int cnt = s_cnt[bb * NC + c];
                    int n = cnt < CS ? cnt : CS;
                    __half2 hini = __half2half2(__ushort_as_half(
                                       (unsigned short)(cnt >= CS ? 0xFC00 : 0)));
                    __half2 s0a = hini, s0b = hini, s1a = hini, s1b = hini;  // 2 streams
                    const unsigned short* bq = &s_buf[(bb * NC + c) * CS];
                    int i = 0;
                    for (; i + 4 <= n; i += 4) {
                        u64 qq = *(const u64*)(bq + i);
                        uint32_t q0 = (uint32_t)(qq) & 0xFFFFu;
                        uint32_t q1 = (uint32_t)(qq >> 16) & 0xFFFFu;
                        uint32_t q2 = (uint32_t)(qq >> 32) & 0xFFFFu;
                        uint32_t q3 = (uint32_t)(qq >> 48) & 0xFFFFu;
                        uint2 r0 = *(const uint2*)(smem + OFF_TAB + q0 * 256u + lane * 8u);
                        uint2 r1 = *(const uint2*)(smem + OFF_TAB + q1 * 256u + lane * 8u);
                        uint2 r2 = *(const uint2*)(smem + OFF_TAB + q2 * 256u + lane * 8u);
                        uint2 r3 = *(const uint2*)(smem + OFF_TAB + q3 * 256u + lane * 8u);
                        s0a = __hmax2(s0a, *(__half2*)&r0.x); s0b = __hmax2(s0b, *(__half2*)&r0.y);
                        s1a = __hmax2(s1a, *(__half2*)&r1.x); s1b = __hmax2(s1b, *(__half2*)&r1.y);
                        s0a = __hmax2(s0a, *(__half2*)&r2.x); s0b = __hmax2(s0b, *(__half2*)&r2.y);
                        s1a = __hmax2(s1a, *(__half2*)&r3.x); s1b = __hmax2(s1b, *(__half2*)&r3.y);
                    }
                    for (; i < n; i++) {
                        uint32_t q = bq[i];
                        uint2 r0 = *(const uint2*)(smem + OFF_TAB + q * 256u + lane * 8u);
                        s0a = __hmax2(s0a, *(__half2*)&r0.x); s0b = __hmax2(s0b, *(__half2*)&r0.y);
                    }
                    __half2 a0 = __hmax2(s0a, s1a);
                    __half2 a1 = __hmax2(s0b, s1b);
                    uint2 st;
                    st.x = *(uint32_t*)&a0; st.y = *(uint32_t*)&a1;
                    *(uint2*)(smem + OFF_M + (bb * NC + c) * WST + lane * 8) = st;
                }
            }
        }
        __syncthreads();

        // ---- mix: warp -> (batch w>>1, i-half w&1); stage via regs + block barrier ----
        {
            const int bb = w >> 1, ph = w & 1;
            if (bb < nb) {
                uint2 v[NC];
#pragma unroll
                for (int j = 0; j < NC; j++)
                    v[j] = *(const uint2*)(smem + OFF_M + (bb * NC + j) * WST + lane * 8);
                u64 mlo[8], mhi[8];
#pragma unroll
                for (int ii = 0; ii < 8; ii++) { mlo[ii] = 0ull; mhi[ii] = 0ull; }
#pragma unroll
                for (int j = 0; j < NC; j++) {
                    float2 flo = __half22float2(*(__half2*)&v[j].x);
                    float2 fhi = __half22float2(*(__half2*)&v[j].y);
                    u64 vlo = pack2(flo.x, flo.y);
                    u64 vhi = pack2(fhi.x, fhi.y);
#pragma unroll
                    for (int ii = 0; ii < 8; ii++) {
                        u64 ap = s_an2[(ph * 8 + ii) * NC + j];
                        ffma2(mlo[ii], vlo, ap);
                        ffma2(mhi[ii], vhi, ap);
                    }
                }
#pragma unroll
                for (int ii = 0; ii < 8; ii++) {
                    float2 l = unpack2(mlo[ii]);
                    float2 h = unpack2(mhi[ii]);
                    __half2 h0 = __floats2half2_rn(l.x, l.y);
                    __half2 h1 = __floats2half2_rn(h.x, h.y);
                    mlo[ii] = ((u64)(*(uint32_t*)&h1) << 32) | (u64)(*(uint32_t*)&h0);
                }
                __syncthreads();  // all reads complete block-wide before in-place writes
#pragma unroll
                for (int ii = 0; ii < 8; ii++) {
                    int r = bb * NC + ph * 8 + ii;
                    uint2 st;
                    st.x = (uint32_t)(mlo[ii] & 0xFFFFFFFFull);
                    st.y = (uint32_t)(mlo[ii] >> 32);
                    *(uint2*)(smem + OFF_M + r * WST + lane * 8) = st;
                }
            } else {
                __syncthreads();  // keep barrier convergent for inactive warps
            }
        }
        __syncthreads();

        // ---- GEMM (16 warps, 16x64 tile each) + pipelined bucket(R+1) on warps 0-7 ----
        {
            const int nr = R + 1;
            const bool doB = (w < 8) && (nr < ROUNDS) && (nr * BPRD + w < nbatch);

            const int rt8 = w >> 1;      // batch in round (16 rows each)
            const int ch  = w & 1;       // 64-col half
            float d[2][4][4];            // 2 col sub-tiles of 32
#pragma unroll
            for (int t = 0; t < 2; t++)
#pragma unroll
                for (int nt = 0; nt < 4; nt++)
#pragma unroll
                    for (int k = 0; k < 4; k++) d[t][nt][k] = 0.f;

            const uint32_t aBase = sb + OFF_M
                + (uint32_t)(rt8 * 16 + (lane & 15)) * WST + (uint32_t)((lane >> 4) * 16);
            const uint32_t bBase0 = sb + OFF_W
                + (uint32_t)(ch * 64 + (lane & 7) + ((lane >> 4) * 8)) * WST
                + (uint32_t)(((lane >> 3) & 1) * 16);
            const uint32_t bBase1 = bBase0 + 16 * WST;
            const uint32_t bBase2 = bBase0 + 32 * WST;
            const uint32_t bBase3 = bBase0 + 48 * WST;

#pragma unroll
            for (int s = 0; s < 8; s++) {
                uint32_t a[4], b0r[4], b1r[4], b2r[4], b3r[4];
                ldsm_x4(a,   aBase  + s * 32);
                ldsm_x4(b0r, bBase0 + s * 32);
                ldsm_x4(b1r, bBase1 + s * 32);
                ldsm_x4(b2r, bBase2 + s * 32);
                ldsm_x4(b3r, bBase3 + s * 32);
                mma16816(d[0][0], a, b0r + 0);
                mma16816(d[0][1], a, b0r + 2);
                mma16816(d[0][2], a, b1r + 0);
                mma16816(d[0][3], a, b1r + 2);
                mma16816(d[1][0], a, b2r + 0);
                mma16816(d[1][1], a, b2r + 2);
                mma16816(d[1][2], a, b3r + 0);
                mma16816(d[1][3], a, b3r + 2);
            }

            // epilogue: bias + direct stores (guarded per batch)
            if (rt8 < nb) {
                const int g = lane >> 2, t4 = lane & 3;
                float* ob = out + (size_t)(b0 + R * BPRD + rt8) * (NC * HID);
                float* o0 = ob + g * HID;
                float* o1 = ob + (g + 8) * HID;
#pragma unroll
                for (int t = 0; t < 2; t++) {
#pragma unroll
                    for (int nt = 0; nt < 4; nt++) {
                        int col = ch * 64 + t * 32 + nt * 8 + 2 * t4;
                        float bv0 = s_bias[col], bv1 = s_bias[col + 1];
                        *(float2*)(o0 + col) = make_float2(d[t][nt][0] + bv0, d[t][nt][1] + bv1);
                        *(float2*)(o1 + col) = make_float2(d[t][nt][2] + bv0, d[t][nt][3] + bv1);
                    }
                }
            }

            // bucket round R+1 (s_buf/s_cnt free: pool(R) consumed them)
            if (doB)
                bucket_match(la, (size_t)(b0 + nr * BPRD + w), w, lane, s_buf, s_cnt, s_tmp);
        }
        __syncthreads();   // M tile consumed + buckets ready before next round
    }
}

extern "C" void kernel_launch(void* const* d_in, const int* in_sizes, int n_in,
                              void* d_out, int out_size) {
    const int*   la   = (const int*)  d_in[0];   // (2048, 512) int32
    const float* adj  = (const float*)d_in[1];   // (16, 16) f32
    const float* qemb = (const float*)d_in[2];   // (513, 128) f32
    const float* W    = (const float*)d_in[3];   // (128, 128) f32
    const float* bias = (const float*)d_in[4];   // (128,) f32
    float* out = (float*)d_out;                  // (2048, 16, 128) f32

    cudaFuncSetAttribute(enc_kernel, cudaFuncAttributeMaxDynamicSharedMemorySize, SMEM_REQ);
    prep_kernel<<<322, 256>>>(adj, W, qemb);
    enc_kernel<<<GRID, THREADS, SMEM_REQ>>>(la, bias, out);
}